// round 1
// baseline (speedup 1.0000x reference)
#include <cuda_runtime.h>
#include <cuda_bf16.h>

// Problem constants (fixed by the dataset)
#define Bk 32
#define Hk 384
#define Wk 384
#define Ck 8
#define NPIX (Bk * Hk * Wk)          // 4,718,592 pixels
#define NELEM ((size_t)NPIX * Ck)    // 37,748,736 floats
#define NUM_ITERS 5

// Tile config for the main iteration kernel
#define TW 32          // tile width  (384 / 32 = 12 blocks in x)
#define TH 12          // tile height (384 / 12 = 32 blocks in y)
#define HALO 3
#define SW (TW + 2 * HALO)   // 38
#define SH (TH + 2 * HALO)   // 18
#define PSTRIDE 12           // padded floats per pixel in smem (48B -> bank-conflict-free LDS.128)
#define NTHREADS 192         // 32 x 6; each thread computes 2 pixels (rows py and py+6)

// Scratch (device globals: allocation-free per harness rules)
__device__ float g_Q[2][NELEM];   // ping-pong q buffers
__device__ float g_U2[NELEM];     // folded unary term: b - u @ W
__device__ float g_K2[49 * 64];   // folded conv kernel: (k*mask) @ W, layout [tap][ci][cd]

// ---------------------------------------------------------------------------
// Packed fp32 FMA: 4x fma.rn.f32x2 accumulating 8 channel outputs for one
// input channel value q. ptxas will not auto-fuse FFMA2 from C++; inline PTX
// is required to reach full fp32 rate on sm_103a.
// ---------------------------------------------------------------------------
__device__ __forceinline__ void mac8(float2* acc, float q, float4 wlo, float4 whi) {
    asm("{\n"
        ".reg .b64 q2, b0, b1, b2, b3, d0, d1, d2, d3;\n"
        "mov.b64 q2, {%8, %8};\n"
        "mov.b64 b0, {%9, %10};\n"
        "mov.b64 b1, {%11, %12};\n"
        "mov.b64 b2, {%13, %14};\n"
        "mov.b64 b3, {%15, %16};\n"
        "mov.b64 d0, {%0, %1};\n"
        "mov.b64 d1, {%2, %3};\n"
        "mov.b64 d2, {%4, %5};\n"
        "mov.b64 d3, {%6, %7};\n"
        "fma.rn.f32x2 d0, q2, b0, d0;\n"
        "fma.rn.f32x2 d1, q2, b1, d1;\n"
        "fma.rn.f32x2 d2, q2, b2, d2;\n"
        "fma.rn.f32x2 d3, q2, b3, d3;\n"
        "mov.b64 {%0, %1}, d0;\n"
        "mov.b64 {%2, %3}, d1;\n"
        "mov.b64 {%4, %5}, d2;\n"
        "mov.b64 {%6, %7}, d3;\n"
        "}"
        : "+f"(acc[0].x), "+f"(acc[0].y), "+f"(acc[1].x), "+f"(acc[1].y),
          "+f"(acc[2].x), "+f"(acc[2].y), "+f"(acc[3].x), "+f"(acc[3].y)
        : "f"(q),
          "f"(wlo.x), "f"(wlo.y), "f"(wlo.z), "f"(wlo.w),
          "f"(whi.x), "f"(whi.y), "f"(whi.z), "f"(whi.w));
}

// ---------------------------------------------------------------------------
// Prep kernel 1: K2[tap][ci][cd] = sum_{co != ci} k[tap][ci][co] * W[co][cd]
// ---------------------------------------------------------------------------
__global__ void prep_weights(const float* __restrict__ k_int,
                             const float* __restrict__ W) {
    int idx = blockIdx.x * blockDim.x + threadIdx.x;
    if (idx >= 49 * 64) return;
    int tap = idx >> 6;
    int ci  = (idx >> 3) & 7;
    int cd  = idx & 7;
    float s = 0.0f;
#pragma unroll
    for (int co = 0; co < 8; co++) {
        if (co == ci) continue;
        s += k_int[(tap * 8 + ci) * 8 + co] * W[co * 8 + cd];
    }
    g_K2[idx] = s;
}

// ---------------------------------------------------------------------------
// Prep kernel 2: per pixel -> q0 = softmax(x); u = -log(max(q0,1e-6));
//                U2 = b - u @ W
// ---------------------------------------------------------------------------
__global__ void prep_pixels(const float* __restrict__ x,
                            const float* __restrict__ W,
                            const float* __restrict__ bvec) {
    long long p = (long long)blockIdx.x * blockDim.x + threadIdx.x;
    if (p >= NPIX) return;
    const float4* xp = (const float4*)(x + (size_t)p * 8);
    float4 a = xp[0], b4 = xp[1];
    float v[8] = {a.x, a.y, a.z, a.w, b4.x, b4.y, b4.z, b4.w};

    float m = v[0];
#pragma unroll
    for (int c = 1; c < 8; c++) m = fmaxf(m, v[c]);
    float e[8], s = 0.0f;
#pragma unroll
    for (int c = 0; c < 8; c++) { e[c] = __expf(v[c] - m); s += e[c]; }
    float inv = 1.0f / s;
    float q[8], u[8];
#pragma unroll
    for (int c = 0; c < 8; c++) {
        q[c] = e[c] * inv;
        u[c] = -__logf(fmaxf(q[c], 1e-6f));
    }
    float4* qp = (float4*)(&g_Q[0][(size_t)p * 8]);
    qp[0] = make_float4(q[0], q[1], q[2], q[3]);
    qp[1] = make_float4(q[4], q[5], q[6], q[7]);

    float u2[8];
#pragma unroll
    for (int cd = 0; cd < 8; cd++) {
        float t = bvec[cd];
#pragma unroll
        for (int c = 0; c < 8; c++) t -= u[c] * W[c * 8 + cd];
        u2[cd] = t;
    }
    float4* up = (float4*)(&g_U2[(size_t)p * 8]);
    up[0] = make_float4(u2[0], u2[1], u2[2], u2[3]);
    up[1] = make_float4(u2[4], u2[5], u2[6], u2[7]);
}

// ---------------------------------------------------------------------------
// Epilogue helper: logits = U2 - penalty; last iter -> write logits;
// otherwise -> write softmax(logits).
// ---------------------------------------------------------------------------
__device__ __forceinline__ void finish_pixel(const float2 acc[4], size_t pix,
                                             float* __restrict__ outbuf, int last) {
    float pen[8] = {acc[0].x, acc[0].y, acc[1].x, acc[1].y,
                    acc[2].x, acc[2].y, acc[3].x, acc[3].y};
    const float4* u2p = (const float4*)(g_U2 + pix * 8);
    float4 ua = u2p[0], ub = u2p[1];
    float l[8];
    l[0] = ua.x - pen[0]; l[1] = ua.y - pen[1];
    l[2] = ua.z - pen[2]; l[3] = ua.w - pen[3];
    l[4] = ub.x - pen[4]; l[5] = ub.y - pen[5];
    l[6] = ub.z - pen[6]; l[7] = ub.w - pen[7];

    float4* op = (float4*)(outbuf + pix * 8);
    if (last) {
        op[0] = make_float4(l[0], l[1], l[2], l[3]);
        op[1] = make_float4(l[4], l[5], l[6], l[7]);
    } else {
        float m = l[0];
#pragma unroll
        for (int c = 1; c < 8; c++) m = fmaxf(m, l[c]);
        float e[8], s = 0.0f;
#pragma unroll
        for (int c = 0; c < 8; c++) { e[c] = __expf(l[c] - m); s += e[c]; }
        float inv = 1.0f / s;
        op[0] = make_float4(e[0] * inv, e[1] * inv, e[2] * inv, e[3] * inv);
        op[1] = make_float4(e[4] * inv, e[5] * inv, e[6] * inv, e[7] * inv);
    }
}

// ---------------------------------------------------------------------------
// Main iteration kernel: fused 7x7 conv (folded kernel) + unary + softmax.
// Block = 32x12 output tile of one image. 192 threads, 2 pixels/thread.
// ---------------------------------------------------------------------------
__global__ void __launch_bounds__(NTHREADS)
mrf_iter(int src, int dst, float* __restrict__ dlogits, int last) {
    __shared__ __align__(16) float sq[SH * SW * PSTRIDE];  // 18*38*12*4 = 32,832 B
    __shared__ __align__(16) float swt[49 * 64];           // 12,544 B

    const int tid = threadIdx.x;
    const int x0 = blockIdx.x * TW;
    const int y0 = blockIdx.y * TH;
    const int bimg = blockIdx.z;

    const float* __restrict__ imgbase =
        &g_Q[src][((size_t)bimg * Hk * Wk) * 8];

    // Load folded conv weights into smem (broadcast-read later)
    for (int i = tid; i < 49 * 64; i += NTHREADS) swt[i] = g_K2[i];

    // Load q tile + halo (zero padding = SAME)
    for (int i = tid; i < SH * SW * 2; i += NTHREADS) {
        int h  = i & 1;
        int xp = (i >> 1) % SW;
        int yp = (i >> 1) / SW;
        int gx = x0 - HALO + xp;
        int gy = y0 - HALO + yp;
        float4 v = make_float4(0.f, 0.f, 0.f, 0.f);
        if (gx >= 0 && gx < Wk && gy >= 0 && gy < Hk)
            v = *(const float4*)(imgbase + ((size_t)gy * Wk + gx) * 8 + h * 4);
        *(float4*)(sq + (yp * SW + xp) * PSTRIDE + h * 4) = v;
    }
    __syncthreads();

    const int px = tid & 31;       // 0..31
    const int py = tid >> 5;       // 0..5 ; pixels at rows py and py+6

    float2 acc0[4] = {{0.f,0.f},{0.f,0.f},{0.f,0.f},{0.f,0.f}};
    float2 acc1[4] = {{0.f,0.f},{0.f,0.f},{0.f,0.f},{0.f,0.f}};

#pragma unroll 1
    for (int dy = 0; dy < 7; ++dy) {
        const float* r0 = sq + ((py + dy) * SW + px) * PSTRIDE;
        const float* r1 = r0 + 6 * SW * PSTRIDE;
        const float4* wrow = (const float4*)(swt + dy * 7 * 64);
#pragma unroll
        for (int dx = 0; dx < 7; ++dx) {
            float4 a0 = *(const float4*)(r0 + dx * PSTRIDE);
            float4 b0 = *(const float4*)(r0 + dx * PSTRIDE + 4);
            float4 a1 = *(const float4*)(r1 + dx * PSTRIDE);
            float4 b1 = *(const float4*)(r1 + dx * PSTRIDE + 4);
            const float4* wp = wrow + dx * 16;
            float4 w0, w1;
            w0 = wp[0];  w1 = wp[1];  mac8(acc0, a0.x, w0, w1); mac8(acc1, a1.x, w0, w1);
            w0 = wp[2];  w1 = wp[3];  mac8(acc0, a0.y, w0, w1); mac8(acc1, a1.y, w0, w1);
            w0 = wp[4];  w1 = wp[5];  mac8(acc0, a0.z, w0, w1); mac8(acc1, a1.z, w0, w1);
            w0 = wp[6];  w1 = wp[7];  mac8(acc0, a0.w, w0, w1); mac8(acc1, a1.w, w0, w1);
            w0 = wp[8];  w1 = wp[9];  mac8(acc0, b0.x, w0, w1); mac8(acc1, b1.x, w0, w1);
            w0 = wp[10]; w1 = wp[11]; mac8(acc0, b0.y, w0, w1); mac8(acc1, b1.y, w0, w1);
            w0 = wp[12]; w1 = wp[13]; mac8(acc0, b0.z, w0, w1); mac8(acc1, b1.z, w0, w1);
            w0 = wp[14]; w1 = wp[15]; mac8(acc0, b0.w, w0, w1); mac8(acc1, b1.w, w0, w1);
        }
    }

    float* outbuf = last ? dlogits : g_Q[dst];
    const size_t pix0 = ((size_t)bimg * Hk + (y0 + py)) * Wk + (x0 + px);
    const size_t pix1 = pix0 + (size_t)6 * Wk;
    finish_pixel(acc0, pix0, outbuf, last);
    finish_pixel(acc1, pix1, outbuf, last);
}

// ---------------------------------------------------------------------------
// Launch: prep (weights + unary/q0), then 5 fused conv+softmax iterations.
// Inputs (metadata order): x, k_internal, k_scale_w, k_scale_b, num_iters.
// num_iters is fixed at 5 by the dataset (device scalar; cannot sync-read
// under graph capture).
// ---------------------------------------------------------------------------
extern "C" void kernel_launch(void* const* d_in, const int* in_sizes, int n_in,
                              void* d_out, int out_size) {
    const float* x          = (const float*)d_in[0];
    const float* k_internal = (const float*)d_in[1];
    const float* k_scale_w  = (const float*)d_in[2];
    const float* k_scale_b  = (const float*)d_in[3];
    float* out = (float*)d_out;

    prep_weights<<<(49 * 64 + 255) / 256, 256>>>(k_internal, k_scale_w);
    prep_pixels<<<NPIX / 256, 256>>>(x, k_scale_w, k_scale_b);

    dim3 grid(Wk / TW, Hk / TH, Bk);   // (12, 32, 32)
    int src = 0;
    for (int it = 0; it < NUM_ITERS; ++it) {
        int last = (it == NUM_ITERS - 1) ? 1 : 0;
        mrf_iter<<<grid, NTHREADS>>>(src, 1 - src, out, last);
        src = 1 - src;
    }
}

// round 3
// speedup vs baseline: 3.5431x; 3.5431x over previous
#include <cuda_runtime.h>
#include <cuda_bf16.h>
#include <cstdint>

// Problem constants
#define Bk 32
#define Hk 384
#define Wk 384
#define NPIX (Bk * Hk * Wk)
#define NELEM ((size_t)NPIX * 8)
#define NUM_ITERS 5

// Tiling
#define CTA_W 64          // pixels in x per CTA (4 warps x 16)
#define RY 4              // output rows per step (per warp, stacked accumulators)
#define TY 48             // output rows per CTA
#define NROWS 10          // rolling window rows (RY + 6 halo)
#define NPXB 72           // buffer pixels per row: 64 + 3 left + 5 right
#define ROWB (NPXB * 16)  // 1152 bytes per row
#define NTHREADS 128

// Device-global scratch (allocation-free)
__device__ __nv_bfloat16 g_Qb[2][NELEM];   // ping-pong q (bf16, pixel-major [pix][8])
__device__ float g_U2[NELEM];              // b - u @ W (fp32)
__device__ float g_K2[49 * 64];            // folded conv kernel [tap][ci][cd]
__device__ uint32_t g_Bfrag[4 * 7 * 2 * 32]; // mma B fragments [p][dy][reg][lane] (bf16x2)

// ---------------------------------------------------------------- PTX helpers
__device__ __forceinline__ uint32_t smem_u32(const void* p) {
    uint32_t a;
    asm("{ .reg .u64 t; cvta.to.shared.u64 t, %1; cvt.u32.u64 %0, t; }"
        : "=r"(a) : "l"(p));
    return a;
}

__device__ __forceinline__ void ldsm_x4(uint32_t& a0, uint32_t& a1,
                                        uint32_t& a2, uint32_t& a3, uint32_t addr) {
    asm volatile("ldmatrix.sync.aligned.m8n8.x4.shared.b16 {%0,%1,%2,%3}, [%4];"
                 : "=r"(a0), "=r"(a1), "=r"(a2), "=r"(a3) : "r"(addr));
}

__device__ __forceinline__ void mma_bf16(float& d0, float& d1, float& d2, float& d3,
                                         uint32_t a0, uint32_t a1, uint32_t a2, uint32_t a3,
                                         uint32_t b0, uint32_t b1) {
    asm volatile(
        "mma.sync.aligned.m16n8k16.row.col.f32.bf16.bf16.f32 "
        "{%0,%1,%2,%3}, {%4,%5,%6,%7}, {%8,%9}, {%0,%1,%2,%3};"
        : "+f"(d0), "+f"(d1), "+f"(d2), "+f"(d3)
        : "r"(a0), "r"(a1), "r"(a2), "r"(a3), "r"(b0), "r"(b1));
}

// ---------------------------------------------------------------- prep kernels
// K2[tap][ci][cd] = sum_{co != ci} k[tap][ci][co] * W[co][cd]
__global__ void prep_weights(const float* __restrict__ k_int,
                             const float* __restrict__ W) {
    int idx = blockIdx.x * blockDim.x + threadIdx.x;
    if (idx >= 49 * 64) return;
    int tap = idx >> 6, ci = (idx >> 3) & 7, cd = idx & 7;
    float s = 0.0f;
#pragma unroll
    for (int co = 0; co < 8; co++) {
        if (co == ci) continue;
        s += k_int[(tap * 8 + ci) * 8 + co] * W[co * 8 + cd];
    }
    g_K2[idx] = s;
}

// Pack B into mma.sync m16n8k16 B-fragment layout.
// Chunk (p, dy): covers taps dx = 2p + j (j = k/8), k%8 = ci, n = output channel.
// Fragment: reg j, lane l -> elements (k0, k0+1), k0 = (l&3)*2 + 8*j, n = l>>2.
__global__ void prep_Bfrag(void) {
    int idx = blockIdx.x * blockDim.x + threadIdx.x;
    if (idx >= 4 * 7 * 2 * 32) return;
    int l  = idx & 31;
    int j  = (idx >> 5) & 1;
    int dy = (idx >> 6) % 7;
    int p  = idx / (32 * 2 * 7);
    int n  = l >> 2;
    int dx = 2 * p + j;
    float v0 = 0.0f, v1 = 0.0f;
    if (dx < 7) {
        int ci = (l & 3) * 2;
        v0 = g_K2[(dy * 7 + dx) * 64 + ci * 8 + n];
        v1 = g_K2[(dy * 7 + dx) * 64 + (ci + 1) * 8 + n];
    }
    __nv_bfloat162 pk = __floats2bfloat162_rn(v0, v1);
    g_Bfrag[((p * 7 + dy) * 2 + j) * 32 + l] = *(uint32_t*)&pk;
}

// per pixel: q0 = softmax(x) (bf16), U2 = b - (-log(clip(q0)))@W (fp32)
__global__ void prep_pixels(const float* __restrict__ x,
                            const float* __restrict__ W,
                            const float* __restrict__ bvec) {
    int p = blockIdx.x * blockDim.x + threadIdx.x;
    if (p >= NPIX) return;
    const float4* xp = (const float4*)(x + (size_t)p * 8);
    float4 a = xp[0], b4 = xp[1];
    float v[8] = {a.x, a.y, a.z, a.w, b4.x, b4.y, b4.z, b4.w};
    float m = v[0];
#pragma unroll
    for (int c = 1; c < 8; c++) m = fmaxf(m, v[c]);
    float e[8], s = 0.0f;
#pragma unroll
    for (int c = 0; c < 8; c++) { e[c] = __expf(v[c] - m); s += e[c]; }
    float inv = 1.0f / s;
    float q[8], u[8];
#pragma unroll
    for (int c = 0; c < 8; c++) {
        q[c] = e[c] * inv;
        u[c] = -__logf(fmaxf(q[c], 1e-6f));
    }
    uint32_t pk[4];
#pragma unroll
    for (int c = 0; c < 4; c++) {
        __nv_bfloat162 t = __floats2bfloat162_rn(q[2 * c], q[2 * c + 1]);
        pk[c] = *(uint32_t*)&t;
    }
    ((uint4*)g_Qb[0])[p] = make_uint4(pk[0], pk[1], pk[2], pk[3]);

    float u2[8];
#pragma unroll
    for (int cd = 0; cd < 8; cd++) {
        float t = bvec[cd];
#pragma unroll
        for (int c = 0; c < 8; c++) t -= u[c] * W[c * 8 + cd];
        u2[cd] = t;
    }
    float4* up = (float4*)(&g_U2[(size_t)p * 8]);
    up[0] = make_float4(u2[0], u2[1], u2[2], u2[3]);
    up[1] = make_float4(u2[4], u2[5], u2[6], u2[7]);
}

// ---------------------------------------------------------------- main kernel
// Each warp: 16 pixels in x, RY=4 output rows per step, K=392 via 28 k16-chunks.
// A-fragments (q rows) loaded once per input row via ldmatrix and reused
// across up to 4 dy positions (4 accumulators).
__global__ void __launch_bounds__(NTHREADS)
mrf_hmma(int src, int dst, float* __restrict__ dlogits, int last) {
    __shared__ __align__(128) __nv_bfloat16 sq[NROWS * NPXB * 8];  // 11520 B
    __shared__ __align__(128) uint32_t sBf[4 * 7 * 2 * 32];        // 7168 B

    const int tid  = threadIdx.x;
    const int warp = tid >> 5;
    const int lane = tid & 31;
    const int x0 = blockIdx.x * CTA_W;
    const int y0 = blockIdx.y * TY;
    const int img = blockIdx.z;

    const uint32_t sq_a = smem_u32(sq);

    // Load B fragments into smem
#pragma unroll
    for (int i = 0; i < 14; i++) sBf[tid + 128 * i] = g_Bfrag[tid + 128 * i];

    const uint4* qsrc = (const uint4*)g_Qb[src];   // one uint4 per pixel
    uint4* sqv = (uint4*)sq;
    const size_t imgoff = (size_t)img * Hk * Wk;

    // Prologue: rows y0-3 .. y0+6 into slots (row mod NROWS)
    for (int i = tid; i < NROWS * NPXB; i += NTHREADS) {
        int row = i / NPXB, px = i % NPXB;
        int yin = y0 - 3 + row;
        int slot = (yin + NROWS) % NROWS;
        int gx = x0 - 3 + px;
        uint4 v = make_uint4(0, 0, 0, 0);
        if (gx >= 0 && gx < Wk && yin >= 0 && yin < Hk)
            v = qsrc[imgoff + (size_t)yin * Wk + gx];
        sqv[slot * NPXB + px] = v;
    }
    __syncthreads();

    // Per-thread constants
    const int toff = (lane & 15) + (lane >> 4);        // ldmatrix row address offset
    const uint32_t abase = sq_a + (16 * warp + toff) * 16;
    const int xq = x0 + 16 * warp + (lane >> 2);       // output pixel (P1); P2 = +8
    const int n0 = (lane & 3) * 2;                     // output channels n0, n0+1

    const int steps = TY / RY;
#pragma unroll 1
    for (int s = 0; s < steps; s++) {
        const int y = y0 + RY * s;

        float acc[4][4];
#pragma unroll
        for (int r = 0; r < 4; r++)
#pragma unroll
            for (int c = 0; c < 4; c++) acc[r][c] = 0.0f;

#pragma unroll
        for (int p = 0; p < 4; p++) {
            uint32_t b[7][2];
#pragma unroll
            for (int dy = 0; dy < 7; dy++) {
#pragma unroll
                for (int j = 0; j < 2; j++)
                    b[dy][j] = sBf[((p * 7 + dy) * 2 + j) * 32 + lane];
            }
#pragma unroll
            for (int i = 0; i < 10; i++) {
                int slot = (y + 7 + i) % NROWS;        // == (y - 3 + i) mod NROWS
                uint32_t a0, a1, a2, a3;
                ldsm_x4(a0, a1, a2, a3, abase + slot * ROWB + p * 32);
#pragma unroll
                for (int r = 0; r < 4; r++) {
                    int dy = i - r;
                    if (dy >= 0 && dy <= 6)
                        mma_bf16(acc[r][0], acc[r][1], acc[r][2], acc[r][3],
                                 a0, a1, a2, a3, b[dy][0], b[dy][1]);
                }
            }
        }

        // Prefetch next RY input rows to registers (overlap with epilogue)
        uint4 pf[3];
        if (s + 1 < steps) {
#pragma unroll
            for (int rep = 0; rep < 3; rep++) {
                int idx = tid + NTHREADS * rep;
                pf[rep] = make_uint4(0, 0, 0, 0);
                if (idx < RY * NPXB) {
                    int row = idx / NPXB, px = idx % NPXB;
                    int yin = y + 7 + row;
                    int gx = x0 - 3 + px;
                    if (gx >= 0 && gx < Wk && yin < Hk)
                        pf[rep] = qsrc[imgoff + (size_t)yin * Wk + gx];
                }
            }
        }

        // Epilogue: logits = U2 - penalty; softmax (or raw logits on last iter)
#pragma unroll
        for (int r = 0; r < 4; r++) {
            const int yy = y + r;
            const size_t pix1 = imgoff + (size_t)yy * Wk + xq;
            const size_t pix2 = pix1 + 8;
            const float2 ua = *(const float2*)(g_U2 + pix1 * 8 + n0);
            const float2 ub = *(const float2*)(g_U2 + pix2 * 8 + n0);
            float l0 = ua.x - acc[r][0];
            float l1 = ua.y - acc[r][1];
            float l2 = ub.x - acc[r][2];
            float l3 = ub.y - acc[r][3];

            if (last) {
                *(float2*)(dlogits + pix1 * 8 + n0) = make_float2(l0, l1);
                *(float2*)(dlogits + pix2 * 8 + n0) = make_float2(l2, l3);
            } else {
                // softmax over 8 channels spread across the 4 lanes of a quad
                float m1 = fmaxf(l0, l1);
                m1 = fmaxf(m1, __shfl_xor_sync(0xffffffffu, m1, 1));
                m1 = fmaxf(m1, __shfl_xor_sync(0xffffffffu, m1, 2));
                float e0 = __expf(l0 - m1), e1 = __expf(l1 - m1);
                float s1 = e0 + e1;
                s1 += __shfl_xor_sync(0xffffffffu, s1, 1);
                s1 += __shfl_xor_sync(0xffffffffu, s1, 2);
                float inv1 = 1.0f / s1;

                float m2 = fmaxf(l2, l3);
                m2 = fmaxf(m2, __shfl_xor_sync(0xffffffffu, m2, 1));
                m2 = fmaxf(m2, __shfl_xor_sync(0xffffffffu, m2, 2));
                float e2 = __expf(l2 - m2), e3 = __expf(l3 - m2);
                float s2 = e2 + e3;
                s2 += __shfl_xor_sync(0xffffffffu, s2, 1);
                s2 += __shfl_xor_sync(0xffffffffu, s2, 2);
                float inv2 = 1.0f / s2;

                __nv_bfloat162 q1 = __floats2bfloat162_rn(e0 * inv1, e1 * inv1);
                __nv_bfloat162 q2 = __floats2bfloat162_rn(e2 * inv2, e3 * inv2);
                uint32_t* qdst = (uint32_t*)g_Qb[dst];
                qdst[pix1 * 4 + (lane & 3)] = *(uint32_t*)&q1;
                qdst[pix2 * 4 + (lane & 3)] = *(uint32_t*)&q2;
            }
        }

        __syncthreads();   // all warps done reading the window
        if (s + 1 < steps) {
#pragma unroll
            for (int rep = 0; rep < 3; rep++) {
                int idx = tid + NTHREADS * rep;
                if (idx < RY * NPXB) {
                    int row = idx / NPXB, px = idx % NPXB;
                    int yin = y + 7 + row;
                    int slot = yin % NROWS;
                    sqv[slot * NPXB + px] = pf[rep];
                }
            }
        }
        __syncthreads();   // new rows visible before next compute
    }
}

// ---------------------------------------------------------------- launch
extern "C" void kernel_launch(void* const* d_in, const int* in_sizes, int n_in,
                              void* d_out, int out_size) {
    const float* x          = (const float*)d_in[0];
    const float* k_internal = (const float*)d_in[1];
    const float* k_scale_w  = (const float*)d_in[2];
    const float* k_scale_b  = (const float*)d_in[3];
    float* out = (float*)d_out;

    prep_weights<<<(49 * 64 + 255) / 256, 256>>>(k_internal, k_scale_w);
    prep_Bfrag<<<7, 256>>>();
    prep_pixels<<<NPIX / 256, 256>>>(x, k_scale_w, k_scale_b);

    dim3 grid(Wk / CTA_W, Hk / TY, Bk);   // (6, 8, 32) = 1536 CTAs
    int src = 0;
    for (int it = 0; it < NUM_ITERS; ++it) {
        int last = (it == NUM_ITERS - 1) ? 1 : 0;
        mrf_hmma<<<grid, NTHREADS>>>(src, 1 - src, out, last);
        src = 1 - src;
    }
}

// round 4
// speedup vs baseline: 4.6927x; 1.3245x over previous
#include <cuda_runtime.h>
#include <cuda_bf16.h>
#include <cstdint>

// Problem constants
#define Bk 32
#define Hk 384
#define Wk 384
#define NPIX (Bk * Hk * Wk)
#define NELEM ((size_t)NPIX * 8)
#define NUM_ITERS 5

// Tiling
#define CTA_W 64          // pixels in x per CTA (4 warps x 16)
#define RY 4              // output rows per step per warp
#define TY 96             // output rows per CTA
#define NROWS 10          // rolling window rows (RY + 6 halo)
#define NPXB 72           // buffer pixels per row: 64 + 3 left + 5 right
#define ROWB (NPXB * 16)  // 1152 bytes per row
#define NTHREADS 128

// Device-global scratch (allocation-free)
__device__ __nv_bfloat16 g_Qb[2][NELEM];     // ping-pong q (bf16, [pix][8])
__device__ float g_U2[NELEM];                // b - u @ W (fp32)
__device__ float g_K2[49 * 64];              // folded conv kernel [tap][ci][cd]
__device__ uint32_t g_Bfrag[4 * 7 * 2 * 32]; // mma B fragments [p][dy][reg][lane]

// ---------------------------------------------------------------- PTX helpers
__device__ __forceinline__ uint32_t smem_u32(const void* p) {
    uint32_t a;
    asm("{ .reg .u64 t; cvta.to.shared.u64 t, %1; cvt.u32.u64 %0, t; }"
        : "=r"(a) : "l"(p));
    return a;
}

__device__ __forceinline__ void ldsm_x4(uint32_t& a0, uint32_t& a1,
                                        uint32_t& a2, uint32_t& a3, uint32_t addr) {
    asm volatile("ldmatrix.sync.aligned.m8n8.x4.shared.b16 {%0,%1,%2,%3}, [%4];"
                 : "=r"(a0), "=r"(a1), "=r"(a2), "=r"(a3) : "r"(addr));
}

__device__ __forceinline__ void mma_bf16(float& d0, float& d1, float& d2, float& d3,
                                         uint32_t a0, uint32_t a1, uint32_t a2, uint32_t a3,
                                         uint32_t b0, uint32_t b1) {
    asm volatile(
        "mma.sync.aligned.m16n8k16.row.col.f32.bf16.bf16.f32 "
        "{%0,%1,%2,%3}, {%4,%5,%6,%7}, {%8,%9}, {%0,%1,%2,%3};"
        : "+f"(d0), "+f"(d1), "+f"(d2), "+f"(d3)
        : "r"(a0), "r"(a1), "r"(a2), "r"(a3), "r"(b0), "r"(b1));
}

// cp.async with zero-fill via src-size operand (0 => no read, zero-fill 16B)
__device__ __forceinline__ void cp16z(uint32_t dst, const void* src, uint32_t sz) {
    asm volatile("cp.async.ca.shared.global [%0], [%1], 16, %2;"
                 :: "r"(dst), "l"(src), "r"(sz) : "memory");
}
#define CP_COMMIT() asm volatile("cp.async.commit_group;" ::: "memory")
#define CP_WAIT0()  asm volatile("cp.async.wait_group 0;" ::: "memory")

// ---------------------------------------------------------------- prep kernels
__global__ void prep_weights(const float* __restrict__ k_int,
                             const float* __restrict__ W) {
    int idx = blockIdx.x * blockDim.x + threadIdx.x;
    if (idx >= 49 * 64) return;
    int tap = idx >> 6, ci = (idx >> 3) & 7, cd = idx & 7;
    float s = 0.0f;
#pragma unroll
    for (int co = 0; co < 8; co++) {
        if (co == ci) continue;
        s += k_int[(tap * 8 + ci) * 8 + co] * W[co * 8 + cd];
    }
    g_K2[idx] = s;
}

// B-fragment pack for m16n8k16: reg j, lane l -> k0=(l&3)*2+8j, n=l>>2
__global__ void prep_Bfrag(void) {
    int idx = blockIdx.x * blockDim.x + threadIdx.x;
    if (idx >= 4 * 7 * 2 * 32) return;
    int l  = idx & 31;
    int j  = (idx >> 5) & 1;
    int dy = (idx >> 6) % 7;
    int p  = idx / (32 * 2 * 7);
    int n  = l >> 2;
    int dx = 2 * p + j;
    float v0 = 0.0f, v1 = 0.0f;
    if (dx < 7) {
        int ci = (l & 3) * 2;
        v0 = g_K2[(dy * 7 + dx) * 64 + ci * 8 + n];
        v1 = g_K2[(dy * 7 + dx) * 64 + (ci + 1) * 8 + n];
    }
    __nv_bfloat162 pk = __floats2bfloat162_rn(v0, v1);
    g_Bfrag[((p * 7 + dy) * 2 + j) * 32 + l] = *(uint32_t*)&pk;
}

__global__ void prep_pixels(const float* __restrict__ x,
                            const float* __restrict__ W,
                            const float* __restrict__ bvec) {
    int p = blockIdx.x * blockDim.x + threadIdx.x;
    if (p >= NPIX) return;
    const float4* xp = (const float4*)(x + (size_t)p * 8);
    float4 a = xp[0], b4 = xp[1];
    float v[8] = {a.x, a.y, a.z, a.w, b4.x, b4.y, b4.z, b4.w};
    float m = v[0];
#pragma unroll
    for (int c = 1; c < 8; c++) m = fmaxf(m, v[c]);
    float e[8], s = 0.0f;
#pragma unroll
    for (int c = 0; c < 8; c++) { e[c] = __expf(v[c] - m); s += e[c]; }
    float inv = 1.0f / s;
    float q[8], u[8];
#pragma unroll
    for (int c = 0; c < 8; c++) {
        q[c] = e[c] * inv;
        u[c] = -__logf(fmaxf(q[c], 1e-6f));
    }
    uint32_t pk[4];
#pragma unroll
    for (int c = 0; c < 4; c++) {
        __nv_bfloat162 t = __floats2bfloat162_rn(q[2 * c], q[2 * c + 1]);
        pk[c] = *(uint32_t*)&t;
    }
    ((uint4*)g_Qb[0])[p] = make_uint4(pk[0], pk[1], pk[2], pk[3]);

    float u2[8];
#pragma unroll
    for (int cd = 0; cd < 8; cd++) {
        float t = bvec[cd];
#pragma unroll
        for (int c = 0; c < 8; c++) t -= u[c] * W[c * 8 + cd];
        u2[cd] = t;
    }
    float4* up = (float4*)(&g_U2[(size_t)p * 8]);
    up[0] = make_float4(u2[0], u2[1], u2[2], u2[3]);
    up[1] = make_float4(u2[4], u2[5], u2[6], u2[7]);
}

// ---------------------------------------------------------------- main kernel
__global__ void __launch_bounds__(NTHREADS, 6)
mrf_hmma(int src, int dst, float* __restrict__ dlogits, int last) {
    __shared__ __align__(128) __nv_bfloat16 sq[NROWS * NPXB * 8];  // 11520 B
    __shared__ __align__(128) uint32_t sBf[4 * 7 * 2 * 32];        // 7168 B

    const int tid  = threadIdx.x;
    const int warp = tid >> 5;
    const int lane = tid & 31;
    const int x0 = blockIdx.x * CTA_W;
    const int y0 = blockIdx.y * TY;
    const int img = blockIdx.z;

    const uint32_t sq_a = smem_u32(sq);

    // B fragments to smem
#pragma unroll
    for (int i = 0; i < 14; i++) sBf[tid + 128 * i] = g_Bfrag[tid + 128 * i];

    const uint4* __restrict__ qsrc = (const uint4*)g_Qb[src];
    const uint32_t imgoff = (uint32_t)img * (Hk * Wk);

    // Prologue: rows y0-3 .. y0+6 via cp.async
    for (int i = tid; i < NROWS * NPXB; i += NTHREADS) {
        int row = i / NPXB, px = i % NPXB;
        int yin = y0 - 3 + row;
        int slot = (yin + NROWS) % NROWS;
        int gx = x0 - 3 + px;
        uint32_t ok = (gx >= 0 && gx < Wk && yin >= 0 && yin < Hk) ? 16u : 0u;
        int gxc = min(max(gx, 0), Wk - 1);
        int yc  = min(max(yin, 0), Hk - 1);
        cp16z(sq_a + (uint32_t)(slot * NPXB + px) * 16,
              qsrc + imgoff + (uint32_t)yc * Wk + gxc, ok);
    }
    CP_COMMIT();
    CP_WAIT0();
    __syncthreads();

    // Per-thread constants
    const int toff = (lane & 15) + (lane >> 4);
    const uint32_t abase = sq_a + (uint32_t)(16 * warp + toff) * 16;
    const int xq = x0 + 16 * warp + (lane >> 2);   // pixel P1; P2 = +8
    const int n0 = (lane & 3) * 2;

    const int steps = TY / RY;
#pragma unroll 1
    for (int s = 0; s < steps; s++) {
        const int y = y0 + RY * s;

        // U2 prefetch for the 4 output rows (overlaps MMA)
        const uint32_t up0 = imgoff + (uint32_t)y * Wk + xq;
        float2 u2a[4], u2b[4];
#pragma unroll
        for (int r = 0; r < 4; r++) {
            u2a[r] = *(const float2*)(g_U2 + ((size_t)(up0 + r * Wk)) * 8 + n0);
            u2b[r] = *(const float2*)(g_U2 + ((size_t)(up0 + r * Wk + 8)) * 8 + n0);
        }

        float acc[4][4];
#pragma unroll
        for (int r = 0; r < 4; r++)
#pragma unroll
            for (int c = 0; c < 4; c++) acc[r][c] = 0.0f;

#pragma unroll
        for (int p = 0; p < 4; p++) {
            uint32_t b[7][2];
#pragma unroll
            for (int dy = 0; dy < 7; dy++) {
#pragma unroll
                for (int j = 0; j < 2; j++)
                    b[dy][j] = sBf[((p * 7 + dy) * 2 + j) * 32 + lane];
            }
#pragma unroll
            for (int i = 0; i < 10; i++) {
                int slot = (y + 7 + i) % NROWS;    // (y - 3 + i) mod NROWS
                uint32_t a0, a1, a2, a3;
                ldsm_x4(a0, a1, a2, a3, abase + (uint32_t)slot * ROWB + p * 32);
#pragma unroll
                for (int r = 0; r < 4; r++) {
                    int dy = i - r;
                    if (dy >= 0 && dy <= 6)
                        mma_bf16(acc[r][0], acc[r][1], acc[r][2], acc[r][3],
                                 a0, a1, a2, a3, b[dy][0], b[dy][1]);
                }
            }
        }

        __syncthreads();   // all warps done reading window slots

        // Issue async copies for the next 4 input rows (overlap epilogue)
        if (s + 1 < steps) {
#pragma unroll
            for (int rep = 0; rep < 3; rep++) {
                int idx = tid + NTHREADS * rep;
                if (idx < RY * NPXB) {
                    int row = idx / NPXB, px = idx % NPXB;
                    int yin = y + 7 + row;
                    int gx = x0 - 3 + px;
                    uint32_t ok = (gx >= 0 && gx < Wk && yin < Hk) ? 16u : 0u;
                    int gxc = min(max(gx, 0), Wk - 1);
                    int yc  = min(yin, Hk - 1);
                    int slot = yin % NROWS;
                    cp16z(sq_a + (uint32_t)(slot * NPXB + px) * 16,
                          qsrc + imgoff + (uint32_t)yc * Wk + gxc, ok);
                }
            }
        }
        CP_COMMIT();

        // Epilogue: logits = U2 - penalty; softmax (or raw logits on last iter)
#pragma unroll
        for (int r = 0; r < 4; r++) {
            const uint32_t pix1 = up0 + (uint32_t)r * Wk;
            const uint32_t pix2 = pix1 + 8;
            float l0 = u2a[r].x - acc[r][0];
            float l1 = u2a[r].y - acc[r][1];
            float l2 = u2b[r].x - acc[r][2];
            float l3 = u2b[r].y - acc[r][3];

            if (last) {
                *(float2*)(dlogits + (size_t)pix1 * 8 + n0) = make_float2(l0, l1);
                *(float2*)(dlogits + (size_t)pix2 * 8 + n0) = make_float2(l2, l3);
            } else {
                float m1 = fmaxf(l0, l1);
                m1 = fmaxf(m1, __shfl_xor_sync(0xffffffffu, m1, 1));
                m1 = fmaxf(m1, __shfl_xor_sync(0xffffffffu, m1, 2));
                float e0 = __expf(l0 - m1), e1 = __expf(l1 - m1);
                float s1 = e0 + e1;
                s1 += __shfl_xor_sync(0xffffffffu, s1, 1);
                s1 += __shfl_xor_sync(0xffffffffu, s1, 2);
                float inv1 = 1.0f / s1;

                float m2 = fmaxf(l2, l3);
                m2 = fmaxf(m2, __shfl_xor_sync(0xffffffffu, m2, 1));
                m2 = fmaxf(m2, __shfl_xor_sync(0xffffffffu, m2, 2));
                float e2 = __expf(l2 - m2), e3 = __expf(l3 - m2);
                float s2 = e2 + e3;
                s2 += __shfl_xor_sync(0xffffffffu, s2, 1);
                s2 += __shfl_xor_sync(0xffffffffu, s2, 2);
                float inv2 = 1.0f / s2;

                __nv_bfloat162 q1 = __floats2bfloat162_rn(e0 * inv1, e1 * inv1);
                __nv_bfloat162 q2 = __floats2bfloat162_rn(e2 * inv2, e3 * inv2);
                uint32_t* qdst = (uint32_t*)g_Qb[dst];
                qdst[(size_t)pix1 * 4 + (lane & 3)] = *(uint32_t*)&q1;
                qdst[(size_t)pix2 * 4 + (lane & 3)] = *(uint32_t*)&q2;
            }
        }

        CP_WAIT0();
        __syncthreads();   // new rows visible before next compute
    }
}

// ---------------------------------------------------------------- launch
extern "C" void kernel_launch(void* const* d_in, const int* in_sizes, int n_in,
                              void* d_out, int out_size) {
    const float* x          = (const float*)d_in[0];
    const float* k_internal = (const float*)d_in[1];
    const float* k_scale_w  = (const float*)d_in[2];
    const float* k_scale_b  = (const float*)d_in[3];
    float* out = (float*)d_out;

    prep_weights<<<(49 * 64 + 255) / 256, 256>>>(k_internal, k_scale_w);
    prep_Bfrag<<<7, 256>>>();
    prep_pixels<<<NPIX / 256, 256>>>(x, k_scale_w, k_scale_b);

    dim3 grid(Wk / CTA_W, Hk / TY, Bk);   // (6, 4, 32) = 768 CTAs
    int src = 0;
    for (int it = 0; it < NUM_ITERS; ++it) {
        int last = (it == NUM_ITERS - 1) ? 1 : 0;
        mrf_hmma<<<grid, NTHREADS>>>(src, 1 - src, out, last);
        src = 1 - src;
    }
}